// round 2
// baseline (speedup 1.0000x reference)
#include <cuda_runtime.h>

#define HH 1024
#define WW 1024
#define NPIX (HH * WW)

// Persistent device-global scratch (no cudaMalloc allowed).
__device__ float4        g_P[NPIX];     // row-normalized 4-neighbor weights (up,down,left,right)
__device__ unsigned char g_seed[NPIX];  // 0 = free, 1/2 = absorbing class
__device__ float2        g_buf[NPIX];   // ping-pong partner of d_out

__global__ __launch_bounds__(256)
void rw_setup_kernel(const float* __restrict__ img,
                     const int* __restrict__ seeds,
                     float2* __restrict__ x0)
{
    int j = blockIdx.x * 32 + threadIdx.x;
    int i = blockIdx.y * blockDim.y + threadIdx.y;
    int idx = i * WW + j;

    float c  = img[idx];
    bool  cb = (c > 0.1f);

    const int di[4] = {-1, 1, 0, 0};
    const int dj[4] = { 0, 0,-1, 1};

    float w[4];
    float rowsum = 0.0f;
#pragma unroll
    for (int d = 0; d < 4; d++) {
        int ni = i + di[d], nj = j + dj[d];
        bool valid = (ni >= 0) && (ni < HH) && (nj >= 0) && (nj < WW);
        int nidx = (valid ? ni : i) * WW + (valid ? nj : j);
        float nb = img[nidx];
        float same = ((nb > 0.1f) != cb) ? 1.0f : 0.0f;
        float diff = c - nb + same;
        float wt = valid ? expf(-1.0f - fabsf(diff)) : 0.0f;
        w[d] = wt;
        rowsum += wt;
    }
    // rowsum > 0 always: every pixel has >=2 valid neighbors, exp() > 0.
    float inv = 1.0f / rowsum;
    float4 p = make_float4(w[0] * inv, w[1] * inv, w[2] * inv, w[3] * inv);
    g_P[idx] = p;

    int s = seeds[idx];
    g_seed[idx] = (unsigned char)s;

    float2 x;
    x.x = (s == 1) ? 1.0f : 0.0f;
    x.y = (s == 2) ? 1.0f : 0.0f;
    x0[idx] = x;
}

__global__ __launch_bounds__(256)
void rw_step_kernel(const float2* __restrict__ xin,
                    float2* __restrict__ xout)
{
    int j = blockIdx.x * 32 + threadIdx.x;
    int i = blockIdx.y * blockDim.y + threadIdx.y;
    int idx = i * WW + j;

    unsigned char s = g_seed[idx];
    float2 o;
    if (s) {
        o.x = (s == 1) ? 1.0f : 0.0f;
        o.y = (s == 2) ? 1.0f : 0.0f;
    } else {
        float4 p = g_P[idx];
        // Clamped indices: out-of-range direction has weight exactly 0.
        int iu = (i == 0)      ? 0      : i - 1;
        int id = (i == HH - 1) ? i      : i + 1;
        int jl = (j == 0)      ? 0      : j - 1;
        int jr = (j == WW - 1) ? j      : j + 1;
        float2 up = xin[iu * WW + j];
        float2 dn = xin[id * WW + j];
        float2 lf = xin[i * WW + jl];
        float2 rt = xin[i * WW + jr];
        o.x = p.x * up.x + p.y * dn.x + p.z * lf.x + p.w * rt.x;
        o.y = p.x * up.y + p.y * dn.y + p.z * lf.y + p.w * rt.y;
    }
    xout[idx] = o;
}

extern "C" void kernel_launch(void* const* d_in, const int* in_sizes, int n_in,
                              void* d_out, int out_size)
{
    const float* img   = (const float*)d_in[0];
    const int*   seeds = (const int*)d_in[1];
    float2*      A     = (float2*)d_out;   // ping buffer; final (100th) write lands here

    float2* B = nullptr;
    cudaGetSymbolAddress((void**)&B, g_buf);

    dim3 blk(32, 8);
    dim3 grd(WW / 32, HH / 8);

    // x0 written into A (= d_out)
    rw_setup_kernel<<<grd, blk>>>(img, seeds, A);

    // 100 Jacobi steps. Parity: step t even reads A writes B; odd reads B writes A.
    // Step 99 (odd) writes A = d_out.
    for (int t = 0; t < 100; t++) {
        const float2* xin  = (t & 1) ? B : A;
        float2*       xout = (t & 1) ? A : B;
        rw_step_kernel<<<grd, blk>>>(xin, xout);
    }
}

// round 3
// speedup vs baseline: 1.0711x; 1.0711x over previous
#include <cuda_runtime.h>

#define HH 1024
#define WW 1024
#define NPIX (HH * WW)

// Persistent device-global scratch (no cudaMalloc allowed).
__device__ float4 g_P[NPIX];    // row-normalized 4-neighbor weights; all-zero at seeds
__device__ float2 g_buf[NPIX];  // ping-pong partner of d_out

__global__ __launch_bounds__(256)
void rw_setup_kernel(const float* __restrict__ img,
                     const int* __restrict__ seeds,
                     float2* __restrict__ x0)
{
    int j = blockIdx.x * 32 + threadIdx.x;
    int i = blockIdx.y * blockDim.y + threadIdx.y;
    int idx = i * WW + j;

    float c  = img[idx];
    bool  cb = (c > 0.1f);

    const int di[4] = {-1, 1, 0, 0};
    const int dj[4] = { 0, 0,-1, 1};

    float w[4];
    float rowsum = 0.0f;
#pragma unroll
    for (int d = 0; d < 4; d++) {
        int ni = i + di[d], nj = j + dj[d];
        bool valid = (ni >= 0) && (ni < HH) && (nj >= 0) && (nj < WW);
        int nidx = (valid ? ni : i) * WW + (valid ? nj : j);
        float nb = img[nidx];
        float same = ((nb > 0.1f) != cb) ? 1.0f : 0.0f;
        float diff = c - nb + same;
        float wt = valid ? expf(-1.0f - fabsf(diff)) : 0.0f;
        w[d] = wt;
        rowsum += wt;
    }
    float inv = 1.0f / rowsum;

    int s = seeds[idx];
    // Seed rows are absorbing: all-zero weights -> self coefficient = 1 exactly.
    float4 p = s ? make_float4(0.f, 0.f, 0.f, 0.f)
                 : make_float4(w[0] * inv, w[1] * inv, w[2] * inv, w[3] * inv);
    g_P[idx] = p;

    float2 x;
    x.x = (s == 1) ? 1.0f : 0.0f;
    x.y = (s == 2) ? 1.0f : 0.0f;
    x0[idx] = x;
}

// Two Jacobi steps per launch via shared-memory temporal blocking.
// Tile 32x32; x loaded with radius-2 halo, P with radius-1 halo.
#define TX 32
#define TY 32
#define XW (TX + 4)   // 36
#define PW (TX + 2)   // 34

__global__ __launch_bounds__(256)
void rw_step2_kernel(const float2* __restrict__ xin,
                     float2* __restrict__ xout)
{
    __shared__ float2 sx[XW][XW];  // 36x36 x,  radius 2
    __shared__ float4 sp[PW][PW];  // 34x34 P,  radius 1
    __shared__ float2 sy[PW][PW];  // 34x34 intermediate (step-1 output)

    const int tid = threadIdx.x;           // 0..255
    const int bx  = blockIdx.x * TX;
    const int by  = blockIdx.y * TY;

    // ---- load x (zero-padded outside image; OOB weight is 0 anyway) ----
#pragma unroll
    for (int k = 0; k < 6; k++) {
        int e = tid + k * 256;
        if (e < XW * XW) {
            int r = e / XW, c = e % XW;
            int gy = by - 2 + r, gx = bx - 2 + c;
            float2 v = make_float2(0.f, 0.f);
            if ((unsigned)gy < HH && (unsigned)gx < WW) v = xin[gy * WW + gx];
            sx[r][c] = v;
        }
    }
    // ---- load P (zero-padded: OOB pixels become absorbing zeros) ----
#pragma unroll
    for (int k = 0; k < 5; k++) {
        int e = tid + k * 256;
        if (e < PW * PW) {
            int r = e / PW, c = e % PW;
            int gy = by - 1 + r, gx = bx - 1 + c;
            float4 p = make_float4(0.f, 0.f, 0.f, 0.f);
            if ((unsigned)gy < HH && (unsigned)gx < WW) p = g_P[gy * WW + gx];
            sp[r][c] = p;
        }
    }
    __syncthreads();

    // ---- step 1: compute y on tile + radius-1 halo (34x34) ----
#pragma unroll
    for (int k = 0; k < 5; k++) {
        int e = tid + k * 256;
        if (e < PW * PW) {
            int r = e / PW, c = e % PW;     // y-space; x-space offset +1
            float4 p  = sp[r][c];
            float2 up = sx[r    ][c + 1];
            float2 dn = sx[r + 2][c + 1];
            float2 lf = sx[r + 1][c    ];
            float2 rt = sx[r + 1][c + 2];
            float2 ct = sx[r + 1][c + 1];
            float self = 1.0f - (p.x + p.y + p.z + p.w);
            float2 o;
            o.x = p.x * up.x + p.y * dn.x + p.z * lf.x + p.w * rt.x + self * ct.x;
            o.y = p.x * up.y + p.y * dn.y + p.z * lf.y + p.w * rt.y + self * ct.y;
            sy[r][c] = o;
        }
    }
    __syncthreads();

    // ---- step 2: compute z on the 32x32 tile, write to global ----
#pragma unroll
    for (int k = 0; k < 4; k++) {
        int e = tid + k * 256;
        int r = e / TX, c = e % TX;         // tile space; y-space offset +1
        float4 p  = sp[r + 1][c + 1];
        float2 up = sy[r    ][c + 1];
        float2 dn = sy[r + 2][c + 1];
        float2 lf = sy[r + 1][c    ];
        float2 rt = sy[r + 1][c + 2];
        float2 ct = sy[r + 1][c + 1];
        float self = 1.0f - (p.x + p.y + p.z + p.w);
        float2 o;
        o.x = p.x * up.x + p.y * dn.x + p.z * lf.x + p.w * rt.x + self * ct.x;
        o.y = p.x * up.y + p.y * dn.y + p.z * lf.y + p.w * rt.y + self * ct.y;
        xout[(by + r) * WW + (bx + c)] = o;
    }
}

extern "C" void kernel_launch(void* const* d_in, const int* in_sizes, int n_in,
                              void* d_out, int out_size)
{
    const float* img   = (const float*)d_in[0];
    const int*   seeds = (const int*)d_in[1];
    float2*      A     = (float2*)d_out;   // ping buffer; final write lands here

    float2* B = nullptr;
    cudaGetSymbolAddress((void**)&B, g_buf);

    {
        dim3 blk(32, 8);
        dim3 grd(WW / 32, HH / 8);
        rw_setup_kernel<<<grd, blk>>>(img, seeds, A);
    }

    // 100 Jacobi steps = 50 double-step kernels.
    // t even: A->B ; t odd: B->A.  t=49 (odd) writes A = d_out.
    dim3 blk(256);
    dim3 grd(WW / TX, HH / TY);
    for (int t = 0; t < 50; t++) {
        const float2* xin  = (t & 1) ? B : A;
        float2*       xout = (t & 1) ? A : B;
        rw_step2_kernel<<<grd, blk>>>(xin, xout);
    }
}

// round 4
// speedup vs baseline: 1.0967x; 1.0239x over previous
#include <cuda_runtime.h>

#define HH 1024
#define WW 1024
#define NPIX (HH * WW)

// Persistent device-global scratch (no cudaMalloc allowed).
__device__ float4 g_P[NPIX];    // row-normalized 4-neighbor weights; all-zero at seeds
__device__ float2 g_buf[NPIX];  // ping-pong partner of d_out

__global__ __launch_bounds__(256)
void rw_setup_kernel(const float* __restrict__ img,
                     const int* __restrict__ seeds,
                     float2* __restrict__ x0)
{
    int j = blockIdx.x * 32 + threadIdx.x;
    int i = blockIdx.y * blockDim.y + threadIdx.y;
    int idx = i * WW + j;

    float c  = img[idx];
    bool  cb = (c > 0.1f);

    const int di[4] = {-1, 1, 0, 0};
    const int dj[4] = { 0, 0,-1, 1};

    float w[4];
    float rowsum = 0.0f;
#pragma unroll
    for (int d = 0; d < 4; d++) {
        int ni = i + di[d], nj = j + dj[d];
        bool valid = (ni >= 0) && (ni < HH) && (nj >= 0) && (nj < WW);
        int nidx = (valid ? ni : i) * WW + (valid ? nj : j);
        float nb = img[nidx];
        float same = ((nb > 0.1f) != cb) ? 1.0f : 0.0f;
        float diff = c - nb + same;
        float wt = valid ? expf(-1.0f - fabsf(diff)) : 0.0f;
        w[d] = wt;
        rowsum += wt;
    }
    float inv = 1.0f / rowsum;

    int s = seeds[idx];
    // Seed rows are absorbing: all-zero weights -> self coefficient = 1 exactly.
    float4 p = s ? make_float4(0.f, 0.f, 0.f, 0.f)
                 : make_float4(w[0] * inv, w[1] * inv, w[2] * inv, w[3] * inv);
    g_P[idx] = p;

    float2 x;
    x.x = (s == 1) ? 1.0f : 0.0f;
    x.y = (s == 2) ? 1.0f : 0.0f;
    x0[idx] = x;
}

// Two Jacobi steps per launch. x staged in smem (radius-2 halo); P read
// directly from L2-resident global (no smem copy). 7 blocks/SM -> single wave.
#define TX 32
#define TY 32
#define XW (TX + 4)   // 36
#define YW (TX + 2)   // 34

__global__ __launch_bounds__(256, 7)
void rw_step2_kernel(const float2* __restrict__ xin,
                     float2* __restrict__ xout)
{
    __shared__ float2 sx[XW][XW];  // 36x36 x, radius 2   (10.4 KB)
    __shared__ float2 sy[YW][YW];  // 34x34 step-1 output ( 9.2 KB)

    const int tid = threadIdx.x;           // 0..255
    const int bx  = blockIdx.x * TX;
    const int by  = blockIdx.y * TY;

    // ---- load x with radius-2 halo (zero-padded outside image) ----
#pragma unroll 1
    for (int e = tid; e < XW * XW; e += 256) {
        int r = e / XW, c = e % XW;
        int gy = by - 2 + r, gx = bx - 2 + c;
        float2 v = make_float2(0.f, 0.f);
        if ((unsigned)gy < HH && (unsigned)gx < WW) v = xin[gy * WW + gx];
        sx[r][c] = v;
    }
    __syncthreads();

    // ---- step 1: compute y on tile + radius-1 halo (34x34); P from global ----
#pragma unroll 1
    for (int e = tid; e < YW * YW; e += 256) {
        int r = e / YW, c = e % YW;          // y-space; x-space offset +1
        int gy = by - 1 + r, gx = bx - 1 + c;
        float4 p = make_float4(0.f, 0.f, 0.f, 0.f);
        if ((unsigned)gy < HH && (unsigned)gx < WW) p = g_P[gy * WW + gx];
        float2 up = sx[r    ][c + 1];
        float2 dn = sx[r + 2][c + 1];
        float2 lf = sx[r + 1][c    ];
        float2 rt = sx[r + 1][c + 2];
        float2 ct = sx[r + 1][c + 1];
        float self = 1.0f - (p.x + p.y + p.z + p.w);
        float2 o;
        o.x = p.x * up.x + p.y * dn.x + p.z * lf.x + p.w * rt.x + self * ct.x;
        o.y = p.x * up.y + p.y * dn.y + p.z * lf.y + p.w * rt.y + self * ct.y;
        sy[r][c] = o;
    }
    __syncthreads();

    // ---- step 2: compute z on the 32x32 tile (always in-bounds), write global ----
#pragma unroll 1
    for (int e = tid; e < TX * TY; e += 256) {
        int r = e / TX, c = e % TX;          // tile space; y-space offset +1
        float4 p = g_P[(by + r) * WW + (bx + c)];
        float2 up = sy[r    ][c + 1];
        float2 dn = sy[r + 2][c + 1];
        float2 lf = sy[r + 1][c    ];
        float2 rt = sy[r + 1][c + 2];
        float2 ct = sy[r + 1][c + 1];
        float self = 1.0f - (p.x + p.y + p.z + p.w);
        float2 o;
        o.x = p.x * up.x + p.y * dn.x + p.z * lf.x + p.w * rt.x + self * ct.x;
        o.y = p.x * up.y + p.y * dn.y + p.z * lf.y + p.w * rt.y + self * ct.y;
        xout[(by + r) * WW + (bx + c)] = o;
    }
}

extern "C" void kernel_launch(void* const* d_in, const int* in_sizes, int n_in,
                              void* d_out, int out_size)
{
    const float* img   = (const float*)d_in[0];
    const int*   seeds = (const int*)d_in[1];
    float2*      A     = (float2*)d_out;   // ping buffer; final write lands here

    float2* B = nullptr;
    cudaGetSymbolAddress((void**)&B, g_buf);

    {
        dim3 blk(32, 8);
        dim3 grd(WW / 32, HH / 8);
        rw_setup_kernel<<<grd, blk>>>(img, seeds, A);
    }

    // 100 Jacobi steps = 50 double-step kernels.
    // t even: A->B ; t odd: B->A.  t=49 (odd) writes A = d_out.
    dim3 blk(256);
    dim3 grd(WW / TX, HH / TY);
    for (int t = 0; t < 50; t++) {
        const float2* xin  = (t & 1) ? B : A;
        float2*       xout = (t & 1) ? A : B;
        rw_step2_kernel<<<grd, blk>>>(xin, xout);
    }
}